// round 9
// baseline (speedup 1.0000x reference)
#include <cuda_runtime.h>
#include <cuda_bf16.h>

// Zero-initialized scratch, 32B-padded per segment (spread atomics across L2
// slices). Max-encoding makes 0 the identity AND results idempotent across
// graph replays -> no init kernel, no reset:
//   g_first_enc[s*8] = max_i (L-1-i)  -> first = L-1-enc
//   g_last[s*8]      = max_i (i)      -> last  = enc
#define MAX_SEG 8192
#define SSTRIDE 8
__device__ int g_first_enc[MAX_SEG * SSTRIDE];
__device__ int g_last[MAX_SEG * SSTRIDE];

// Scan: exactly one int4 per thread, one wave, no loops -> minimal CTA tail
// (PDL releases the gather at scan COMPLETION, so the tail is critical path).
__global__ void __launch_bounds__(256) scan_kernel(
        const int* __restrict__ mask, int L, int n) {
    int v   = blockIdx.x * blockDim.x + threadIdx.x;   // int4 index
    int nv4 = L >> 2;
    if (v < nv4) {
        const int4* m4 = (const int4*)mask;
        int4 ids = m4[v];
        int i0 = v * 4;
        #pragma unroll
        for (int k = 0; k < 4; k++) {
            int id = (&ids.x)[k];
            if (id >= 0 && id < n) {
                atomicMax(&g_first_enc[id * SSTRIDE], (L - 1) - (i0 + k));
                atomicMax(&g_last[id * SSTRIDE], i0 + k);
            }
        }
    }
    // tail for L % 4 != 0 (not hit for L=32768)
    int i = (nv4 << 2) + v;
    if (v < (L - (nv4 << 2))) {
        int id = mask[i];
        if (id >= 0 && id < n) {
            atomicMax(&g_first_enc[id * SSTRIDE], (L - 1) - i);
            atomicMax(&g_last[id * SSTRIDE], i);
        }
    }
}

// Gather: 2 segments per block, 4 independent row-loads batched per thread.
// Launched with PDL; cudaGridDependencySynchronize() waits for scan
// completion (implicit trigger -> atomics fully visible).
__global__ void __launch_bounds__(256) gather_kernel(
        const float* __restrict__ x, float* __restrict__ out, int L, int H, int n) {
    int seg0 = blockIdx.x * 2;
    int seg1 = seg0 + 1;
    int nvec = H / 4;                      // 256 for H=1024
    int tid  = threadIdx.x;

    float4* __restrict__ o0 = (float4*)(out + (size_t)seg0 * (2 * H));
    float4* __restrict__ o1 = (float4*)(out + (size_t)seg1 * (2 * H));

    cudaGridDependencySynchronize();       // wait for scan_kernel

    bool has1 = seg1 < n;
    int fi0 = (L - 1) - g_first_enc[seg0 * SSTRIDE];
    int li0 = g_last[seg0 * SSTRIDE];
    const float4* f0 = (const float4*)(x + (size_t)fi0 * H);
    const float4* l0 = (const float4*)(x + (size_t)li0 * H);
    const float4* f1 = f0;
    const float4* l1 = l0;
    if (has1) {
        int fi1 = (L - 1) - g_first_enc[seg1 * SSTRIDE];
        int li1 = g_last[seg1 * SSTRIDE];
        f1 = (const float4*)(x + (size_t)fi1 * H);
        l1 = (const float4*)(x + (size_t)li1 * H);
    }

    for (int t = tid; t < nvec; t += blockDim.x) {
        float4 a = f0[t];                  // 4 independent loads in flight
        float4 b = l0[t];
        float4 c = f1[t];
        float4 d = l1[t];
        o0[t]        = a;
        o0[nvec + t] = b;
        if (has1) {
            o1[t]        = c;
            o1[nvec + t] = d;
        }
    }
}

extern "C" void kernel_launch(void* const* d_in, const int* in_sizes, int n_in,
                              void* d_out, int out_size) {
    const float* x    = (const float*)d_in[0];
    const int*   mask = (const int*)d_in[1];
    float*       out  = (float*)d_out;

    int L = in_sizes[1];          // B*S = 32768
    int H = in_sizes[0] / L;      // 1024
    int n = out_size / (2 * H);   // 512
    if (n > MAX_SEG) n = MAX_SEG;

    int scan_threads = (L + 3) / 4;                  // one int4 per thread
    int scan_blocks  = (scan_threads + 255) / 256;   // 32 for L=32768
    scan_kernel<<<scan_blocks, 256>>>(mask, L, n);

    // Gather with PDL: overlap its launch ramp with scan execution.
    cudaLaunchConfig_t cfg = {};
    cfg.gridDim  = dim3((unsigned)((n + 1) / 2));
    cfg.blockDim = dim3(256);
    cfg.dynamicSmemBytes = 0;
    cfg.stream = 0;
    cudaLaunchAttribute attrs[1];
    attrs[0].id = cudaLaunchAttributeProgrammaticStreamSerialization;
    attrs[0].val.programmaticStreamSerializationAllowed = 1;
    cfg.attrs = attrs;
    cfg.numAttrs = 1;
    cudaLaunchKernelEx(&cfg, gather_kernel, x, out, L, H, n);
}

// round 10
// speedup vs baseline: 1.2368x; 1.2368x over previous
#include <cuda_runtime.h>
#include <cuda_bf16.h>
#include <limits.h>

// Single self-sufficient kernel: each block finds the first/last occurrence
// of ITS OWN segment id by scanning the (L2-resident, broadcast-shared)
// mask in windows, then copies the two rows. No global scratch, no atomics
// on global memory, no inter-kernel dependency, trivially replay-safe.
//
// Window scan is general: it loops until found. For the bench input
// (ids cycle 0..N_SEG), both hits land in the first window from each end.

#define NTHR 256
#define WIN  1024   // ids per scan window (4 KB)

__global__ void __launch_bounds__(NTHR) fused_gather_kernel(
        const float* __restrict__ x,
        const int*   __restrict__ mask,
        float*       __restrict__ out,
        int L, int H) {
    const int seg = blockIdx.x;
    const int tid = threadIdx.x;

    __shared__ int s_first, s_last;

    // ---- find FIRST occurrence: forward windows ----
    int first = INT_MAX;
    for (int base = 0; base < L && first == INT_MAX; base += WIN) {
        if (tid == 0) s_first = INT_MAX;
        __syncthreads();
        int lim = base + WIN < L ? base + WIN : L;
        int local = INT_MAX;
        for (int i = base + tid; i < lim; i += NTHR) {
            if (mask[i] == seg) { local = i; break; }   // ascending -> min hit
        }
        if (local != INT_MAX) atomicMin(&s_first, local);
        __syncthreads();
        first = s_first;
        __syncthreads();
    }

    // ---- find LAST occurrence: backward windows ----
    int last = -1;
    for (int end = L; end > 0 && last < 0; end -= WIN) {
        int start = end - WIN > 0 ? end - WIN : 0;
        if (tid == 0) s_last = -1;
        __syncthreads();
        int local = -1;
        for (int i = start + tid; i < end; i += NTHR) {
            if (mask[i] == seg) local = i;              // ascending overwrite -> max hit
        }
        if (local >= 0) atomicMax(&s_last, local);
        __syncthreads();
        last = s_last;
        __syncthreads();
    }

    if (first == INT_MAX || last < 0) return;           // segment absent

    // ---- copy first/last rows (float4; H=1024 -> exactly 1 iter/thread) ----
    const float4* __restrict__ f4 = (const float4*)(x + (size_t)first * H);
    const float4* __restrict__ l4 = (const float4*)(x + (size_t)last  * H);
    float4* __restrict__ o4 = (float4*)(out + (size_t)seg * (2 * H));

    int nvec = H / 4;
    for (int t = tid; t < nvec; t += NTHR) {
        float4 a = f4[t];
        float4 b = l4[t];
        o4[t]        = a;
        o4[nvec + t] = b;
    }
}

extern "C" void kernel_launch(void* const* d_in, const int* in_sizes, int n_in,
                              void* d_out, int out_size) {
    const float* x    = (const float*)d_in[0];
    const int*   mask = (const int*)d_in[1];
    float*       out  = (float*)d_out;

    int L = in_sizes[1];          // B*S = 32768
    int H = in_sizes[0] / L;      // 1024
    int n = out_size / (2 * H);   // 512

    fused_gather_kernel<<<n, NTHR>>>(x, mask, out, L, H);
}

// round 11
// speedup vs baseline: 1.5971x; 1.2913x over previous
#include <cuda_runtime.h>
#include <cuda_bf16.h>
#include <limits.h>

// Single self-sufficient kernel: block `seg` finds first/last occurrence of
// its own segment id by scanning the L2-resident mask (broadcast across
// blocks), then copies the two rows. No global scratch, no global atomics,
// trivially graph-replay-safe.
//
// Scan: forward + backward windows processed in the SAME round with all
// window loads issued unconditionally (8 independent LDGs in flight per
// thread) — no load chains, 2 barriers per round. For the bench input both
// hits land in round 0; the loop keeps it correct for arbitrary masks.

#define NTHR 256
#define WIN  1024            // ids per window (4 per thread)
#define KPT  (WIN / NTHR)    // 4

__global__ void __launch_bounds__(NTHR) fused_gather_kernel(
        const float* __restrict__ x,
        const int*   __restrict__ mask,
        float*       __restrict__ out,
        int L, int H) {
    const int seg = blockIdx.x;
    const int tid = threadIdx.x;

    __shared__ int s_first, s_last;
    if (tid == 0) { s_first = INT_MAX; s_last = -1; }

    int first = INT_MAX, last = -1;
    int fbase = 0;           // forward window base
    int bend  = L;           // backward window end (exclusive)

    while (first == INT_MAX || last < 0) {
        // ---- batched, unconditional loads for both windows ----
        int fidx[KPT], fval[KPT], bidx[KPT], bval[KPT];
        bool doF = (first == INT_MAX) && (fbase < L);
        bool doB = (last < 0) && (bend > 0);
        int bstart = bend - WIN > 0 ? bend - WIN : 0;
        #pragma unroll
        for (int k = 0; k < KPT; k++) {
            fidx[k] = fbase + tid + k * NTHR;
            bidx[k] = bstart + tid + k * NTHR;
            fval[k] = (doF && fidx[k] < L)    ? __ldg(mask + fidx[k]) : -1;
            bval[k] = (doB && bidx[k] < bend) ? __ldg(mask + bidx[k]) : -1;
        }
        // ---- local reduce ----
        int lf = INT_MAX, lb = -1;
        #pragma unroll
        for (int k = 0; k < KPT; k++) {
            if (fval[k] == seg && fidx[k] < lf) lf = fidx[k];
            if (bval[k] == seg && bidx[k] > lb) lb = bidx[k];
        }
        if (lf != INT_MAX) atomicMin(&s_first, lf);
        if (lb >= 0)       atomicMax(&s_last, lb);
        __syncthreads();
        first = s_first;
        last  = s_last;
        fbase += WIN;
        bend  = bstart;
        if ((first == INT_MAX && fbase >= L) && (last < 0 && bend <= 0)) break;
        __syncthreads();     // protect s_first/s_last reuse next round
    }

    if (first == INT_MAX || last < 0) return;   // segment absent

    // ---- copy first/last rows (float4; H=1024 -> 1 iter/thread) ----
    const float4* __restrict__ f4 = (const float4*)(x + (size_t)first * H);
    const float4* __restrict__ l4 = (const float4*)(x + (size_t)last  * H);
    float4* __restrict__ o4 = (float4*)(out + (size_t)seg * (2 * H));

    int nvec = H / 4;
    for (int t = tid; t < nvec; t += NTHR) {
        float4 a = __ldg(f4 + t);
        float4 b = __ldg(l4 + t);
        __stcs(o4 + t,        a);   // streaming store: out is write-once
        __stcs(o4 + nvec + t, b);
    }
}

extern "C" void kernel_launch(void* const* d_in, const int* in_sizes, int n_in,
                              void* d_out, int out_size) {
    const float* x    = (const float*)d_in[0];
    const int*   mask = (const int*)d_in[1];
    float*       out  = (float*)d_out;

    int L = in_sizes[1];          // B*S = 32768
    int H = in_sizes[0] / L;      // 1024
    int n = out_size / (2 * H);   // 512

    fused_gather_kernel<<<n, NTHR>>>(x, mask, out, L, H);
}